// round 2
// baseline (speedup 1.0000x reference)
#include <cuda_runtime.h>
#include <cuda_bf16.h>

// Problem constants
#define S_LEN 2048
#define B_SZ  16
#define H_DIM 1024

// Scratch: energy[B][H]  (no cudaMalloc allowed)
__device__ float g_energy[B_SZ * H_DIM];

// ---------------------------------------------------------------------------
// Kernel 1 v2: energy[b][h] = sum_j state[b][j] * W[h][j] + bias[h]
// One WARP per h-row; each lane keeps 16 accumulators (one per b).
// W is read exactly once from DRAM; state (64 KB) is L1/L2 resident.
// grid = 128 blocks x 256 threads (8 warps) -> 1024 warps = 1024 rows.
// ---------------------------------------------------------------------------
__global__ void __launch_bounds__(256)
energy_kernel(const float* __restrict__ lds,
              const float* __restrict__ W,
              const float* __restrict__ bias)
{
    const int warp = threadIdx.x >> 5;
    const int lane = threadIdx.x & 31;
    const int h    = blockIdx.x * 8 + warp;

    const float4* wrow = reinterpret_cast<const float4*>(W + (size_t)h * H_DIM);
    const float4* st   = reinterpret_cast<const float4*>(lds);  // [B][H/4]

    float acc[B_SZ];
    #pragma unroll
    for (int b = 0; b < B_SZ; ++b) acc[b] = 0.f;

    #pragma unroll
    for (int i = 0; i < 8; ++i) {                 // 8 * 32 lanes * 4 = 1024
        const int idx = lane + i * 32;
        const float4 w = wrow[idx];
        #pragma unroll
        for (int b = 0; b < B_SZ; ++b) {
            const float4 s = st[b * (H_DIM / 4) + idx];
            acc[b] += w.x * s.x + w.y * s.y + w.z * s.z + w.w * s.w;
        }
    }

    const float bh = bias[h];
    #pragma unroll
    for (int b = 0; b < B_SZ; ++b) {
        float v = acc[b];
        #pragma unroll
        for (int off = 16; off > 0; off >>= 1)
            v += __shfl_xor_sync(0xFFFFFFFF, v, off);
        if (lane == 0)
            g_energy[b * H_DIM + h] = v + bh;
    }
}

// ---------------------------------------------------------------------------
// Kernel 2 (HBM-bound, near roofline already):
// scores[s][b] = sum_h enc[s][b][h] * energy[b][h]
// One block per row (s*B+b). 128 threads, each 2x float4 = 8 floats.
// ---------------------------------------------------------------------------
__global__ void __launch_bounds__(128, 16)
score_kernel(const float* __restrict__ enc, float* __restrict__ out)
{
    const int row = blockIdx.x;          // s*B + b
    const int b   = row & (B_SZ - 1);
    const int t   = threadIdx.x;

    const float4* e = reinterpret_cast<const float4*>(enc + (size_t)row * H_DIM);
    const float4* g = reinterpret_cast<const float4*>(g_energy + (size_t)b * H_DIM);

    float4 a0 = e[t];
    float4 a1 = e[t + 128];
    float4 w0 = g[t];
    float4 w1 = g[t + 128];

    float acc = a0.x * w0.x + a0.y * w0.y + a0.z * w0.z + a0.w * w0.w
              + a1.x * w1.x + a1.y * w1.y + a1.z * w1.z + a1.w * w1.w;

    #pragma unroll
    for (int off = 16; off > 0; off >>= 1)
        acc += __shfl_xor_sync(0xFFFFFFFF, acc, off);

    __shared__ float red[4];
    const int warp = t >> 5;
    const int lane = t & 31;
    if (lane == 0) red[warp] = acc;
    __syncthreads();
    if (t == 0)
        out[row] = red[0] + red[1] + red[2] + red[3];
}

// ---------------------------------------------------------------------------
// Kernel 3: softmax over S (axis 0) per batch column b, in place on d_out.
// ---------------------------------------------------------------------------
__global__ void softmax_kernel(float* __restrict__ out)
{
    const int b = blockIdx.x;
    const int t = threadIdx.x;
    const int VPT = S_LEN / 256;   // 8

    float v[VPT];
    float mx = -3.402823466e38f;
    #pragma unroll
    for (int i = 0; i < VPT; ++i) {
        v[i] = out[(size_t)(t + i * 256) * B_SZ + b];
        mx = fmaxf(mx, v[i]);
    }

    __shared__ float sm[8];
    #pragma unroll
    for (int off = 16; off > 0; off >>= 1)
        mx = fmaxf(mx, __shfl_xor_sync(0xFFFFFFFF, mx, off));
    const int warp = t >> 5, lane = t & 31;
    if (lane == 0) sm[warp] = mx;
    __syncthreads();
    if (warp == 0) {
        float m = (lane < 8) ? sm[lane] : -3.402823466e38f;
        #pragma unroll
        for (int off = 4; off > 0; off >>= 1)
            m = fmaxf(m, __shfl_xor_sync(0xFFFFFFFF, m, off));
        if (lane == 0) sm[0] = m;
    }
    __syncthreads();
    mx = sm[0];
    __syncthreads();

    float sum = 0.f;
    #pragma unroll
    for (int i = 0; i < VPT; ++i) {
        v[i] = __expf(v[i] - mx);
        sum += v[i];
    }
    #pragma unroll
    for (int off = 16; off > 0; off >>= 1)
        sum += __shfl_xor_sync(0xFFFFFFFF, sum, off);
    if (lane == 0) sm[warp] = sum;
    __syncthreads();
    if (warp == 0) {
        float s = (lane < 8) ? sm[lane] : 0.f;
        #pragma unroll
        for (int off = 4; off > 0; off >>= 1)
            s += __shfl_xor_sync(0xFFFFFFFF, s, off);
        if (lane == 0) sm[0] = s;
    }
    __syncthreads();
    const float inv = 1.0f / sm[0];

    #pragma unroll
    for (int i = 0; i < VPT; ++i)
        out[(size_t)(t + i * 256) * B_SZ + b] = v[i] * inv;
}

// ---------------------------------------------------------------------------
extern "C" void kernel_launch(void* const* d_in, const int* in_sizes, int n_in,
                              void* d_out, int out_size)
{
    const float* enc  = (const float*)d_in[0];  // [S,B,H]
    const float* lds  = (const float*)d_in[1];  // [2,1,B,H]
    const float* W    = (const float*)d_in[2];  // [H,H]
    const float* bias = (const float*)d_in[3];  // [H]
    float* out = (float*)d_out;                 // [1,1,S,B] == [S,B]

    energy_kernel<<<H_DIM / 8, 256>>>(lds, W, bias);
    score_kernel<<<S_LEN * B_SZ, 128>>>(enc, out);
    softmax_kernel<<<B_SZ, 256>>>(out);
}

// round 3
// speedup vs baseline: 1.2143x; 1.2143x over previous
#include <cuda_runtime.h>
#include <cuda_bf16.h>

#define S_LEN 2048
#define B_SZ  16
#define H_DIM 1024

__device__ float g_energy[B_SZ * H_DIM];

// ---------------------------------------------------------------------------
// Kernel 1 v3: energy[b][h] = sum_j state[b][j]*W[h][j] + bias[h]
// Block = 512 threads (16 warps, warp = b), lanes sweep j (coalesced).
// Each block handles R=4 consecutive h rows; state row held in registers.
// grid = 256 blocks -> ~1.7 waves, all W DRAM misses overlap.
// ---------------------------------------------------------------------------
#define R_ROWS 4
__global__ void __launch_bounds__(512)
energy_kernel(const float* __restrict__ lds,
              const float* __restrict__ W,
              const float* __restrict__ bias)
{
    const int warp = threadIdx.x >> 5;   // = b
    const int lane = threadIdx.x & 31;
    const int h0   = blockIdx.x * R_ROWS;

    const float4* st = reinterpret_cast<const float4*>(lds);       // [B][H/4]
    const float4* W4 = reinterpret_cast<const float4*>(W);         // [H][H/4]

    // state row b in registers (32 regs)
    float4 s[8];
    #pragma unroll
    for (int i = 0; i < 8; ++i)
        s[i] = st[warp * (H_DIM / 4) + lane + i * 32];

    #pragma unroll
    for (int r = 0; r < R_ROWS; ++r) {
        const int h = h0 + r;
        float acc = 0.f;
        #pragma unroll
        for (int i = 0; i < 8; ++i) {
            const float4 w = W4[(size_t)h * (H_DIM / 4) + lane + i * 32];
            acc += w.x * s[i].x + w.y * s[i].y + w.z * s[i].z + w.w * s[i].w;
        }
        #pragma unroll
        for (int off = 16; off > 0; off >>= 1)
            acc += __shfl_xor_sync(0xFFFFFFFF, acc, off);
        if (lane == 0)
            g_energy[warp * H_DIM + h] = acc + bias[h];
    }
}

// ---------------------------------------------------------------------------
// Kernel 2 v2: scores[s][b] = sum_h enc[s][b][h] * energy[b][h]
// One block per (b, 8-row s-chunk): energy row loaded once into registers,
// reused for 8 encoder rows. 128 threads, 16 independent float4 enc loads.
// ---------------------------------------------------------------------------
#define VPS 8
__global__ void __launch_bounds__(128, 8)
score_kernel(const float* __restrict__ enc, float* __restrict__ out)
{
    const int b  = blockIdx.x & (B_SZ - 1);
    const int s0 = (blockIdx.x >> 4) * VPS;
    const int t  = threadIdx.x;

    const float4* e4 = reinterpret_cast<const float4*>(enc);
    const float4* g4 = reinterpret_cast<const float4*>(g_energy);

    const float4 g0 = g4[b * (H_DIM / 4) + t];
    const float4 g1 = g4[b * (H_DIM / 4) + 128 + t];

    float acc[VPS];
    #pragma unroll
    for (int i = 0; i < VPS; ++i) {
        const size_t row = ((size_t)(s0 + i) * B_SZ + b) * (H_DIM / 4);
        const float4 a0 = e4[row + t];
        const float4 a1 = e4[row + 128 + t];
        acc[i] = a0.x * g0.x + a0.y * g0.y + a0.z * g0.z + a0.w * g0.w
               + a1.x * g1.x + a1.y * g1.y + a1.z * g1.z + a1.w * g1.w;
    }

    #pragma unroll
    for (int i = 0; i < VPS; ++i)
        #pragma unroll
        for (int off = 16; off > 0; off >>= 1)
            acc[i] += __shfl_xor_sync(0xFFFFFFFF, acc[i], off);

    __shared__ float red[4][VPS];
    const int warp = t >> 5;
    const int lane = t & 31;
    if (lane == 0) {
        #pragma unroll
        for (int i = 0; i < VPS; ++i)
            red[warp][i] = acc[i];
    }
    __syncthreads();
    if (t < VPS)
        out[(size_t)(s0 + t) * B_SZ + b] =
            red[0][t] + red[1][t] + red[2][t] + red[3][t];
}

// ---------------------------------------------------------------------------
// Kernel 3: softmax over S per batch column b, in place on d_out.
// ---------------------------------------------------------------------------
__global__ void softmax_kernel(float* __restrict__ out)
{
    const int b = blockIdx.x;
    const int t = threadIdx.x;
    const int VPT = S_LEN / 256;   // 8

    float v[VPT];
    float mx = -3.402823466e38f;
    #pragma unroll
    for (int i = 0; i < VPT; ++i) {
        v[i] = out[(size_t)(t + i * 256) * B_SZ + b];
        mx = fmaxf(mx, v[i]);
    }

    __shared__ float sm[8];
    #pragma unroll
    for (int off = 16; off > 0; off >>= 1)
        mx = fmaxf(mx, __shfl_xor_sync(0xFFFFFFFF, mx, off));
    const int warp = t >> 5, lane = t & 31;
    if (lane == 0) sm[warp] = mx;
    __syncthreads();
    if (warp == 0) {
        float m = (lane < 8) ? sm[lane] : -3.402823466e38f;
        #pragma unroll
        for (int off = 4; off > 0; off >>= 1)
            m = fmaxf(m, __shfl_xor_sync(0xFFFFFFFF, m, off));
        if (lane == 0) sm[0] = m;
    }
    __syncthreads();
    mx = sm[0];
    __syncthreads();

    float sum = 0.f;
    #pragma unroll
    for (int i = 0; i < VPT; ++i) {
        v[i] = __expf(v[i] - mx);
        sum += v[i];
    }
    #pragma unroll
    for (int off = 16; off > 0; off >>= 1)
        sum += __shfl_xor_sync(0xFFFFFFFF, sum, off);
    if (lane == 0) sm[warp] = sum;
    __syncthreads();
    if (warp == 0) {
        float s = (lane < 8) ? sm[lane] : 0.f;
        #pragma unroll
        for (int off = 4; off > 0; off >>= 1)
            s += __shfl_xor_sync(0xFFFFFFFF, s, off);
        if (lane == 0) sm[0] = s;
    }
    __syncthreads();
    const float inv = 1.0f / sm[0];

    #pragma unroll
    for (int i = 0; i < VPT; ++i)
        out[(size_t)(t + i * 256) * B_SZ + b] = v[i] * inv;
}

// ---------------------------------------------------------------------------
extern "C" void kernel_launch(void* const* d_in, const int* in_sizes, int n_in,
                              void* d_out, int out_size)
{
    const float* enc  = (const float*)d_in[0];  // [S,B,H]
    const float* lds  = (const float*)d_in[1];  // [2,1,B,H]
    const float* W    = (const float*)d_in[2];  // [H,H]
    const float* bias = (const float*)d_in[3];  // [H]
    float* out = (float*)d_out;                 // [1,1,S,B] == [S,B]

    energy_kernel<<<H_DIM / R_ROWS, 512>>>(lds, W, bias);
    score_kernel<<<(S_LEN / VPS) * B_SZ, 128>>>(enc, out);
    softmax_kernel<<<B_SZ, 256>>>(out);
}